// round 1
// baseline (speedup 1.0000x reference)
#include <cuda_runtime.h>
#include <cuda_bf16.h>
#include <cstdint>

// RadiusGraph with PBC minimum-image wrap.
// out layout: [0 .. 3*N*N)  disp  [N,N,3] f32
//             [3*N*N .. 4*N*N) mask [N,N]  f32 (0/1)

#define R_CUT 5.0f
#define MAX_B 64

__device__ float g_cell[MAX_B * 9];   // cell[b][r][c] row-major
__device__ float g_invT[MAX_B * 9];   // inv(cell[b]^T)[r][c] row-major

// One thread per batch: build inv(cell^T) in double precision.
__global__ void precompute_inv_kernel(const float* __restrict__ cell, int B) {
    int b = threadIdx.x;
    if (b >= B) return;
    double m[3][3];
#pragma unroll
    for (int r = 0; r < 3; r++)
#pragma unroll
        for (int c = 0; c < 3; c++)
            m[r][c] = (double)cell[b * 9 + r * 3 + c];

    // A = cell^T
    double a00 = m[0][0], a01 = m[1][0], a02 = m[2][0];
    double a10 = m[0][1], a11 = m[1][1], a12 = m[2][1];
    double a20 = m[0][2], a21 = m[1][2], a22 = m[2][2];

    double C00 =  a11 * a22 - a12 * a21;
    double C01 = -(a10 * a22 - a12 * a20);
    double C02 =  a10 * a21 - a11 * a20;
    double det = a00 * C00 + a01 * C01 + a02 * C02;
    double id  = 1.0 / det;

    double inv[3][3];
    inv[0][0] = C00 * id;
    inv[1][0] = C01 * id;
    inv[2][0] = C02 * id;
    inv[0][1] = (a02 * a21 - a01 * a22) * id;   // C10
    inv[1][1] = (a00 * a22 - a02 * a20) * id;   // C11
    inv[2][1] = -(a00 * a21 - a01 * a20) * id;  // C12
    inv[0][2] = (a01 * a12 - a02 * a11) * id;   // C20
    inv[1][2] = -(a00 * a12 - a02 * a10) * id;  // C21
    inv[2][2] = (a00 * a11 - a01 * a10) * id;   // C22

#pragma unroll
    for (int r = 0; r < 3; r++)
#pragma unroll
        for (int c = 0; c < 3; c++) {
            g_cell[b * 9 + r * 3 + c] = (float)m[r][c];
            g_invT[b * 9 + r * 3 + c] = (float)inv[r][c];
        }
}

// Block: 128 threads; each thread handles 4 consecutive j for a fixed row i.
// grid.x = N / 512, grid.y = N.
__global__ __launch_bounds__(128) void radius_graph_kernel(
    const float* __restrict__ pos,
    const int*   __restrict__ batch,
    float* __restrict__ out,
    int n)
{
    const int i  = blockIdx.y;
    const int j0 = (blockIdx.x * blockDim.x + threadIdx.x) * 4;

    const int   bi  = __ldg(&batch[i]);
    const float pix = __ldg(&pos[i * 3 + 0]);
    const float piy = __ldg(&pos[i * 3 + 1]);
    const float piz = __ldg(&pos[i * 3 + 2]);

    float cm[9], tm[9];
#pragma unroll
    for (int k = 0; k < 9; k++) {
        cm[k] = g_cell[bi * 9 + k];
        tm[k] = g_invT[bi * 9 + k];
    }

    // Load 4 positions (12 floats) as 3 float4 (pos base is 16B-aligned, j0%4==0).
    const float4* p4 = reinterpret_cast<const float4*>(pos + (size_t)j0 * 3);
    float4 q0 = p4[0], q1 = p4[1], q2 = p4[2];
    float px[4] = {q0.x, q0.w, q1.z, q2.y};
    float py[4] = {q0.y, q1.x, q1.w, q2.z};
    float pz[4] = {q0.z, q1.y, q2.x, q2.w};

    int4 b4 = *reinterpret_cast<const int4*>(batch + j0);
    int  bj[4] = {b4.x, b4.y, b4.z, b4.w};

    float dx[4], dy[4], dz[4], mk[4];
#pragma unroll
    for (int k = 0; k < 4; k++) {
        float ddx = pix - px[k];
        float ddy = piy - py[k];
        float ddz = piz - pz[k];

        float s0 = tm[0] * ddx + tm[1] * ddy + tm[2] * ddz;
        float s1 = tm[3] * ddx + tm[4] * ddy + tm[5] * ddz;
        float s2 = tm[6] * ddx + tm[7] * ddy + tm[8] * ddz;
        s0 = rintf(s0); s1 = rintf(s1); s2 = rintf(s2);

        ddx -= cm[0] * s0 + cm[1] * s1 + cm[2] * s2;
        ddy -= cm[3] * s0 + cm[4] * s1 + cm[5] * s2;
        ddz -= cm[6] * s0 + cm[7] * s1 + cm[8] * s2;

        bool ok = (bi == bj[k]) && (i != (j0 + k)) &&
                  (sqrtf(ddx * ddx + ddy * ddy + ddz * ddz) < R_CUT);
        dx[k] = ok ? ddx : 0.0f;
        dy[k] = ok ? ddy : 0.0f;
        dz[k] = ok ? ddz : 0.0f;
        mk[k] = ok ? 1.0f : 0.0f;
    }

    float* od = out + (size_t)i * n * 3 + (size_t)j0 * 3;
    reinterpret_cast<float4*>(od)[0] = make_float4(dx[0], dy[0], dz[0], dx[1]);
    reinterpret_cast<float4*>(od)[1] = make_float4(dy[1], dz[1], dx[2], dy[2]);
    reinterpret_cast<float4*>(od)[2] = make_float4(dz[2], dx[3], dy[3], dz[3]);

    float* om = out + (size_t)3 * n * n + (size_t)i * n + j0;
    reinterpret_cast<float4*>(om)[0] = make_float4(mk[0], mk[1], mk[2], mk[3]);
}

extern "C" void kernel_launch(void* const* d_in, const int* in_sizes, int n_in,
                              void* d_out, int out_size) {
    const float* pos   = (const float*)d_in[0];
    const float* cell  = (const float*)d_in[1];
    const int*   batch = (const int*)d_in[2];
    float* out = (float*)d_out;

    const int n = in_sizes[0] / 3;      // 4096
    const int B = in_sizes[1] / 9;      // 8

    precompute_inv_kernel<<<1, 32>>>(cell, B);

    dim3 block(128);
    dim3 grid(n / 512, n);
    radius_graph_kernel<<<grid, block>>>(pos, batch, out, n);
}